// round 2
// baseline (speedup 1.0000x reference)
#include <cuda_runtime.h>
#include <math.h>

#define MAXK 128
#define BLOCK 256
#define APT 2   // anchors per thread

// Accumulators: 0 focal_fs, 1 focal_ss, 2 iou_fs, 3 iou_ss, 4 cnt_fs, 5 cnt_ss
__device__ double g_acc[6];
__device__ unsigned int g_done = 0;

__device__ __forceinline__ float focal_term(float l, float t) {
    // stable BCE-with-logits focal term (alpha=0.25, gamma=2)
    float ce = fmaxf(l, 0.f) - l * t + log1pf(expf(-fabsf(l)));
    float p  = 1.f / (1.f + expf(-l));
    float pt = p * t + (1.f - p) * (1.f - t);
    float at = 0.25f * t + 0.75f * (1.f - t);
    float m  = 1.f - pt;
    return at * ce * m * m;
}

// IoU of pred box (xywh) vs gt box (xyxy with precomputed area)
__device__ __forceinline__ float pred_iou(float px, float py, float pw, float ph,
                                          float4 g, float garea) {
    float px2 = px + pw, py2 = py + ph;
    float lx = fmaxf(px, g.x), ly = fmaxf(py, g.y);
    float rx = fminf(px2, g.z), ry = fminf(py2, g.w);
    float w = fmaxf(rx - lx, 0.f), h = fmaxf(ry - ly, 0.f);
    float inter = w * h;
    return __fdividef(inter, pw * ph + garea - inter);
}

__global__ __launch_bounds__(BLOCK)
void ainno_fused_kernel(const float* __restrict__ fs,
                        const float* __restrict__ ss,
                        const float* __restrict__ anchors,
                        const float* __restrict__ gt,
                        float* __restrict__ out,
                        int B, int C, int K)
{
    __shared__ float4 s_gbox[MAXK];   // gt xyxy
    __shared__ float  s_garea[MAXK];  // gt area
    __shared__ float  s_red[6][BLOCK / 32];

    const int tid = threadIdx.x;
    const int b   = blockIdx.y;

    if (tid < K) {
        const float* g = gt + ((size_t)b * K + tid) * 4;
        float x = g[0], y = g[1], w = g[2], h = g[3];
        s_gbox[tid]  = make_float4(x, y, x + w, y + h);
        s_garea[tid] = w * h;
    }
    __syncthreads();

    const int cbase = blockIdx.x * (BLOCK * APT) + tid;

    float ax1[APT], ay1[APT], ax2[APT], ay2[APT], area[APT], best[APT];
    bool  valid[APT];
    #pragma unroll
    for (int j = 0; j < APT; j++) {
        int c = cbase + j * BLOCK;
        valid[j] = (c < C);
        if (valid[j]) {
            float4 a = *(const float4*)(anchors + (size_t)c * 4);
            ax1[j] = a.x; ay1[j] = a.y;
            ax2[j] = a.x + a.z; ay2[j] = a.y + a.w;
            area[j] = a.z * a.w;
        } else {
            // degenerate: guarantees inter=0, d>0
            ax1[j] = 4e9f; ay1[j] = 4e9f; ax2[j] = -4e9f; ay2[j] = -4e9f;
            area[j] = 1.f;
        }
        best[j] = 0.f;
    }

    // Pass 1: max IoU per anchor (no index tracking -> no select chain).
    #pragma unroll 4
    for (int i = 0; i < K; i++) {
        float4 g = s_gbox[i];
        float ga = s_garea[i];
        #pragma unroll
        for (int j = 0; j < APT; j++) {
            float lx = fmaxf(ax1[j], g.x), ly = fmaxf(ay1[j], g.y);
            float rx = fminf(ax2[j], g.z), ry = fminf(ay2[j], g.w);
            float w  = fmaxf(rx - lx, 0.f);
            float h  = fmaxf(ry - ly, 0.f);
            float inter = w * h;
            float d = area[j] + ga - inter;       // union > 0 always
            best[j] = fmaxf(best[j], __fdividef(inter, d));
        }
    }

    float acc[6] = {0.f, 0.f, 0.f, 0.f, 0.f, 0.f};

    #pragma unroll
    for (int j = 0; j < APT; j++) {
        if (!valid[j]) continue;
        int c = cbase + j * BLOCK;
        float ts = best[j];

        size_t pbase = ((size_t)b * C + c) * 6;
        float2 f0 = *(const float2*)(fs + pbase);
        float2 f1 = *(const float2*)(fs + pbase + 2);
        float2 f2 = *(const float2*)(fs + pbase + 4);
        float2 s0 = *(const float2*)(ss + pbase);
        float2 s1 = *(const float2*)(ss + pbase + 2);
        float2 s2 = *(const float2*)(ss + pbase + 4);

        acc[0] += focal_term(f2.x, ts);
        acc[1] += focal_term(s2.x, ts);

        if (ts >= 0.5f) {
            // Pass 2 (rare): recover argmax index with exact-ish cross-multiply
            // compare (strict > keeps first-max, matching jnp.argmax).
            float bi = 0.f, bu = 1.f; int bk = 0;
            for (int i = 0; i < K; i++) {
                float4 g = s_gbox[i];
                float lx = fmaxf(ax1[j], g.x), ly = fmaxf(ay1[j], g.y);
                float rx = fminf(ax2[j], g.z), ry = fminf(ay2[j], g.w);
                float w  = fmaxf(rx - lx, 0.f);
                float h  = fmaxf(ry - ly, 0.f);
                float inter = w * h;
                float uni   = area[j] + s_garea[i] - inter;
                if (inter * bu > bi * uni) { bi = inter; bu = uni; bk = i; }
            }
            float4 g = s_gbox[bk];
            float ga = s_garea[bk];
            acc[5] += 1.f;
            acc[3] += -logf(pred_iou(s0.x, s0.y, s1.x, s1.y, g, ga));
            if (ts >= 0.7f) {
                acc[4] += 1.f;
                acc[2] += -logf(pred_iou(f0.x, f0.y, f1.x, f1.y, g, ga));
            }
        }
    }

    // ---- block reduction of 6 scalars ----
    #pragma unroll
    for (int jj = 0; jj < 6; jj++) {
        float x = acc[jj];
        #pragma unroll
        for (int off = 16; off > 0; off >>= 1)
            x += __shfl_down_sync(0xFFFFFFFFu, x, off);
        acc[jj] = x;
    }
    int warp = tid >> 5, lane = tid & 31;
    if (lane == 0) {
        #pragma unroll
        for (int jj = 0; jj < 6; jj++) s_red[jj][warp] = acc[jj];
    }
    __syncthreads();

    if (warp == 0) {
        const int nw = BLOCK / 32;
        float x = 0.f;
        #pragma unroll
        for (int jj = 0; jj < 6; jj++) {
            x = (lane < nw) ? s_red[jj][lane] : 0.f;
            #pragma unroll
            for (int off = 4; off > 0; off >>= 1)
                x += __shfl_down_sync(0xFFFFFFFFu, x, off);
            if (lane == 0) atomicAdd(&g_acc[jj], (double)x);
        }
        if (lane == 0) {
            __threadfence();
            unsigned total = gridDim.x * gridDim.y;
            unsigned prev = atomicAdd(&g_done, 1u);
            if (prev == total - 1) {
                // last block: all g_acc updates are visible
                volatile double* ga = g_acc;
                double N      = (double)B * (double)C;
                double cnt_fs = ga[4] < 1.0 ? 1.0 : ga[4];
                double cnt_ss = ga[5] < 1.0 ? 1.0 : ga[5];
                double res = (ga[1] / N) / cnt_ss
                           + (ga[0] / N) / cnt_fs
                           + (ga[3] / cnt_ss)
                           + (ga[2] / cnt_fs);
                out[0] = (float)res;
                // reset for next graph replay
                #pragma unroll
                for (int jj = 0; jj < 6; jj++) g_acc[jj] = 0.0;
                __threadfence();
                g_done = 0u;
            }
        }
    }
}

extern "C" void kernel_launch(void* const* d_in, const int* in_sizes, int n_in,
                              void* d_out, int out_size) {
    const float* fs      = (const float*)d_in[0];
    const float* ss      = (const float*)d_in[1];
    const float* anchors = (const float*)d_in[2];
    const float* gt      = (const float*)d_in[3];
    float* out = (float*)d_out;

    int C = in_sizes[2] / 4;
    int B = in_sizes[0] / (6 * C);
    int K = in_sizes[3] / (4 * B);

    dim3 grid((C + BLOCK * APT - 1) / (BLOCK * APT), B);
    ainno_fused_kernel<<<grid, BLOCK>>>(fs, ss, anchors, gt, out, B, C, K);
}

// round 3
// speedup vs baseline: 1.6196x; 1.6196x over previous
#include <cuda_runtime.h>
#include <math.h>

#define MAXK 128
#define BLOCK 256
#define APT 4   // anchors per thread

#define RS 0x1p-10f   // exact power-of-2 coordinate scale; IoU is scale-invariant

// Accumulators: 0 focal_fs, 1 focal_ss, 2 iou_fs, 3 iou_ss, 4 cnt_fs, 5 cnt_ss
__device__ double g_acc[6];
__device__ unsigned int g_done = 0;

// sub with saturate-to-[0,1]: single FADD.SAT on the fma pipe
__device__ __forceinline__ float sub_sat(float a, float b) {
    float r;
    asm("sub.rn.sat.f32 %0, %1, %2;" : "=f"(r) : "f"(a), "f"(b));
    return r;
}

__device__ __forceinline__ float focal_term(float l, float t) {
    // stable BCE-with-logits focal term (alpha=0.25, gamma=2)
    float ce = fmaxf(l, 0.f) - l * t + log1pf(expf(-fabsf(l)));
    float p  = 1.f / (1.f + expf(-l));
    float pt = p * t + (1.f - p) * (1.f - t);
    float at = 0.25f * t + 0.75f * (1.f - t);
    float m  = 1.f - pt;
    return at * ce * m * m;
}

// IoU of pred box (xywh, pre-scaled) vs gt box (xyxy pre-scaled, area pre-scaled)
__device__ __forceinline__ float pred_iou(float px, float py, float pw, float ph,
                                          float4 g, float garea) {
    float px2 = px + pw, py2 = py + ph;
    float lx = fmaxf(px, g.x), ly = fmaxf(py, g.y);
    float rx = fminf(px2, g.z), ry = fminf(py2, g.w);
    float w = sub_sat(rx, lx), h = sub_sat(ry, ly);
    float inter = w * h;
    return __fdividef(inter, pw * ph + garea - inter);
}

__global__ __launch_bounds__(BLOCK)
void ainno_fused_kernel(const float* __restrict__ fs,
                        const float* __restrict__ ss,
                        const float* __restrict__ anchors,
                        const float* __restrict__ gt,
                        float* __restrict__ out,
                        int B, int C, int K)
{
    __shared__ float4 s_gbox[MAXK];   // gt xyxy (scaled)
    __shared__ float  s_garea[MAXK];  // gt area (scaled^2)
    __shared__ float  s_red[6][BLOCK / 32];

    const int tid = threadIdx.x;
    const int b   = blockIdx.y;

    if (tid < K) {
        const float* g = gt + ((size_t)b * K + tid) * 4;
        float x = g[0] * RS, y = g[1] * RS, w = g[2] * RS, h = g[3] * RS;
        s_gbox[tid]  = make_float4(x, y, x + w, y + h);
        s_garea[tid] = w * h;
    }
    __syncthreads();

    const int cbase = blockIdx.x * (BLOCK * APT) + tid;

    float ax1[APT], ay1[APT], ax2[APT], ay2[APT], area[APT];
    float bi[APT], bS[APT];
    int   bk[APT];
    #pragma unroll
    for (int j = 0; j < APT; j++) {
        int c = cbase + j * BLOCK;
        if (c < C) {
            float4 a = *(const float4*)(anchors + (size_t)c * 4);
            float x = a.x * RS, y = a.y * RS, w = a.z * RS, h = a.w * RS;
            ax1[j] = x; ay1[j] = y; ax2[j] = x + w; ay2[j] = y + h;
            area[j] = w * h;
        } else {
            // degenerate: inter always 0
            ax1[j] = 8.f; ay1[j] = 8.f; ax2[j] = -8.f; ay2[j] = -8.f;
            area[j] = 1.f;
        }
        bi[j] = 0.f; bS[j] = 1.f; bk[j] = 0;
    }

    // Pass 1: inline argmax via S-compare (iou = i/(S-i) is monotone in i/S;
    // ordering by inter_i*bS > bi*S_i is exactly the iou ordering; strict >
    // keeps the FIRST max, matching jnp.argmax).
    #pragma unroll 4
    for (int i = 0; i < K; i++) {
        float4 g = s_gbox[i];
        float ga = s_garea[i];
        #pragma unroll
        for (int j = 0; j < APT; j++) {
            float lx = fmaxf(ax1[j], g.x), ly = fmaxf(ay1[j], g.y);
            float rx = fminf(ax2[j], g.z), ry = fminf(ay2[j], g.w);
            float w  = sub_sat(rx, lx);
            float h  = sub_sat(ry, ly);
            float inter = w * h;
            float S  = area[j] + ga;
            bool better = inter * bS[j] > bi[j] * S;
            bi[j] = better ? inter : bi[j];
            bS[j] = better ? S     : bS[j];
            bk[j] = better ? i     : bk[j];
        }
    }

    float acc[6] = {0.f, 0.f, 0.f, 0.f, 0.f, 0.f};

    #pragma unroll
    for (int j = 0; j < APT; j++) {
        int c = cbase + j * BLOCK;
        if (c >= C) continue;
        float ts = __fdividef(bi[j], bS[j] - bi[j]);  // max IoU (0 if none)

        size_t pbase = ((size_t)b * C + c) * 6;
        float fl = __ldg(fs + pbase + 4);   // fs logit
        float sl = __ldg(ss + pbase + 4);   // ss logit

        acc[0] += focal_term(fl, ts);
        acc[1] += focal_term(sl, ts);

        if (ts >= 0.5f) {
            float4 g = s_gbox[bk[j]];
            float ga = s_garea[bk[j]];
            float sx = __ldg(ss + pbase)     * RS;
            float sy = __ldg(ss + pbase + 1) * RS;
            float sw = __ldg(ss + pbase + 2) * RS;
            float sh = __ldg(ss + pbase + 3) * RS;
            acc[5] += 1.f;
            acc[3] += -logf(pred_iou(sx, sy, sw, sh, g, ga));
            if (ts >= 0.7f) {
                float fx = __ldg(fs + pbase)     * RS;
                float fy = __ldg(fs + pbase + 1) * RS;
                float fw = __ldg(fs + pbase + 2) * RS;
                float fh = __ldg(fs + pbase + 3) * RS;
                acc[4] += 1.f;
                acc[2] += -logf(pred_iou(fx, fy, fw, fh, g, ga));
            }
        }
    }

    // ---- block reduction of 6 scalars ----
    #pragma unroll
    for (int jj = 0; jj < 6; jj++) {
        float x = acc[jj];
        #pragma unroll
        for (int off = 16; off > 0; off >>= 1)
            x += __shfl_down_sync(0xFFFFFFFFu, x, off);
        acc[jj] = x;
    }
    int warp = tid >> 5, lane = tid & 31;
    if (lane == 0) {
        #pragma unroll
        for (int jj = 0; jj < 6; jj++) s_red[jj][warp] = acc[jj];
    }
    __syncthreads();

    if (warp == 0) {
        const int nw = BLOCK / 32;
        #pragma unroll
        for (int jj = 0; jj < 6; jj++) {
            float x = (lane < nw) ? s_red[jj][lane] : 0.f;
            #pragma unroll
            for (int off = 4; off > 0; off >>= 1)
                x += __shfl_down_sync(0xFFFFFFFFu, x, off);
            if (lane == 0) atomicAdd(&g_acc[jj], (double)x);
        }
        if (lane == 0) {
            __threadfence();
            unsigned total = gridDim.x * gridDim.y;
            unsigned prev = atomicAdd(&g_done, 1u);
            if (prev == total - 1) {
                volatile double* ga = g_acc;
                double N      = (double)B * (double)C;
                double cnt_fs = ga[4] < 1.0 ? 1.0 : ga[4];
                double cnt_ss = ga[5] < 1.0 ? 1.0 : ga[5];
                double res = (ga[1] / N) / cnt_ss
                           + (ga[0] / N) / cnt_fs
                           + (ga[3] / cnt_ss)
                           + (ga[2] / cnt_fs);
                out[0] = (float)res;
                #pragma unroll
                for (int jj = 0; jj < 6; jj++) g_acc[jj] = 0.0;
                __threadfence();
                g_done = 0u;
            }
        }
    }
}

extern "C" void kernel_launch(void* const* d_in, const int* in_sizes, int n_in,
                              void* d_out, int out_size) {
    const float* fs      = (const float*)d_in[0];
    const float* ss      = (const float*)d_in[1];
    const float* anchors = (const float*)d_in[2];
    const float* gt      = (const float*)d_in[3];
    float* out = (float*)d_out;

    int C = in_sizes[2] / 4;
    int B = in_sizes[0] / (6 * C);
    int K = in_sizes[3] / (4 * B);

    dim3 grid((C + BLOCK * APT - 1) / (BLOCK * APT), B);
    ainno_fused_kernel<<<grid, BLOCK>>>(fs, ss, anchors, gt, out, B, C, K);
}